// round 15
// baseline (speedup 1.0000x reference)
#include <cuda_runtime.h>
#include <cuda_fp16.h>
#include <cstdint>
#include <cstddef>

// Problem constants
#define EMBED 1024
#define SEQ   16384   // 4 * 4096 tokens
#define HEADS 16

// ---------------------------------------------------------------------------
// Scratch (allocation-free rule: __device__ globals)
// ---------------------------------------------------------------------------
__device__ __align__(1024) __half g_Xh [SEQ * EMBED];         // x -> fp16
__device__ __align__(1024) __half g_WT [3 * EMBED * EMBED];   // [Wq;Wk;Wv]^T fp16 [n][k]
__device__ __align__(1024) __half g_WoT[EMBED * EMBED];       // Wo^T fp16 [n][k]
__device__ __align__(1024) __half g_Qh [SEQ * EMBED];         // pre-scaled by 1/32
__device__ __align__(1024) __half g_Kh [SEQ * EMBED];
__device__ __align__(1024) __half g_Vh [SEQ * EMBED];
__device__ __align__(1024) __half g_AOh[SEQ * EMBED];

__device__ __forceinline__ uint32_t h2_bits(__half2 h) {
    union { __half2 h; uint32_t u; } cvt;
    cvt.h = h;
    return cvt.u;
}

// ---------------------------------------------------------------------------
// Fused prep: z<4 -> transpose+convert one weight matrix (32x32 tile grid);
//             z>=4 -> convert an x chunk to fp16 (8 z-slices x 1024 blocks).
// Block: (32, 8) = 256 threads for both paths.
// ---------------------------------------------------------------------------
__global__ void prep_k(const float* __restrict__ x,
                       const float* __restrict__ Wq,
                       const float* __restrict__ Wk,
                       const float* __restrict__ Wv,
                       const float* __restrict__ Wo,
                       __half* __restrict__ Xh,
                       __half* __restrict__ WT,     // 3*E*E
                       __half* __restrict__ WoT) {  // E*E
    const int z = blockIdx.z;
    if (z >= 4) {
        // x -> fp16: 8 halves per thread
        const int tid = threadIdx.y * 32 + threadIdx.x;
        const int blk = (z - 4) * 1024 + blockIdx.y * 32 + blockIdx.x;
        const int i   = blk * 256 + tid;          // uint4 (8-half) index
        const float4* src = (const float4*)x;
        float4 v0 = src[2 * i], v1 = src[2 * i + 1];
        uint4 u;
        u.x = h2_bits(__floats2half2_rn(v0.x, v0.y));
        u.y = h2_bits(__floats2half2_rn(v0.z, v0.w));
        u.z = h2_bits(__floats2half2_rn(v1.x, v1.y));
        u.w = h2_bits(__floats2half2_rn(v1.z, v1.w));
        ((uint4*)Xh)[i] = u;
        return;
    }
    const float* src = (z == 0) ? Wq : (z == 1) ? Wk : (z == 2) ? Wv : Wo;
    __half* dst = (z == 3) ? WoT : WT + (size_t)z * EMBED * EMBED;

    __shared__ float t[32][33];
    const int tx = threadIdx.x, ty = threadIdx.y;
    const int n  = blockIdx.x * 32 + tx;
    const int k0 = blockIdx.y * 32;
    #pragma unroll
    for (int j = 0; j < 32; j += 8)
        t[ty + j][tx] = src[(size_t)(k0 + ty + j) * EMBED + n];
    __syncthreads();
    const int ok  = k0 + tx;
    const int on0 = blockIdx.x * 32;
    #pragma unroll
    for (int j = 0; j < 32; j += 8)
        dst[(size_t)(on0 + ty + j) * EMBED + ok] = __float2half_rn(t[tx][ty + j]);
}

// ---------------------------------------------------------------------------
// FP16 tensor-core GEMM: C[M,N] = A[M,K] @ B[N,K]^T
// Tile 128x128, 8 warps (2M x 4N) of 64x32, BK=32, FIVE-stage cp.async,
// occ 2 (2 x 100KB = 200KB <= 228KB). Single __syncthreads per iteration:
// wait -> sync -> prefetch(kt+4) -> compute. Race-free: stage (kt+4)%5 ==
// (kt-1)%5 was last read in iteration kt-1; the barrier at top of kt
// guarantees all warps passed it.
// ---------------------------------------------------------------------------
#define BM 128
#define BN 128
#define BK 32
#define PITCH 80                       // bytes per smem row (64B data + pad)
#define A_BYTES (BM * PITCH)           // 10240
#define B_BYTES (BN * PITCH)           // 10240
#define STAGE   (A_BYTES + B_BYTES)    // 20480
#define NSTAGE  5
#define GEMM_SMEM (NSTAGE * STAGE)     // 102400

__device__ __forceinline__ void cpa16(void* dst, const void* src) {
    uint32_t d = (uint32_t)__cvta_generic_to_shared(dst);
    asm volatile("cp.async.cg.shared.global [%0], [%1], 16;\n"
                 :: "r"(d), "l"(src));
}

__device__ __forceinline__ void ldsm4(uint32_t* r, uint32_t saddr) {
    asm volatile("ldmatrix.sync.aligned.m8n8.x4.shared.b16 {%0,%1,%2,%3}, [%4];"
                 : "=r"(r[0]), "=r"(r[1]), "=r"(r[2]), "=r"(r[3]) : "r"(saddr));
}

__device__ __forceinline__ void ldsm4t(uint32_t* r, uint32_t saddr) {
    asm volatile("ldmatrix.sync.aligned.m8n8.x4.trans.shared.b16 {%0,%1,%2,%3}, [%4];"
                 : "=r"(r[0]), "=r"(r[1]), "=r"(r[2]), "=r"(r[3]) : "r"(saddr));
}

__device__ __forceinline__ void mma16816(float* c, const uint32_t* a,
                                         uint32_t b0, uint32_t b1) {
    asm volatile("mma.sync.aligned.m16n8k16.row.col.f32.f16.f16.f32 "
        "{%0,%1,%2,%3}, {%4,%5,%6,%7}, {%8,%9}, {%0,%1,%2,%3};\n"
        : "+f"(c[0]), "+f"(c[1]), "+f"(c[2]), "+f"(c[3])
        : "r"(a[0]), "r"(a[1]), "r"(a[2]), "r"(a[3]), "r"(b0), "r"(b1));
}

__device__ __forceinline__ void load_stage(char* sm, int s,
        const __half* __restrict__ A, const __half* __restrict__ Bw,
        int m0, int ngl0, int k0, int tid) {
    char* As = sm + s * STAGE;
    char* Bs = As + A_BYTES;
    const int row = tid >> 2;            // 0..63
    const int c   = (tid & 3) * 16;      // byte offset in 64B row data
    const int kh  = k0 + (tid & 3) * 8;  // half offset
    #pragma unroll
    for (int j = 0; j < 2; j++) {        // A: 128 rows
        int r = row + j * 64;
        cpa16(As + r * PITCH + c, A + (size_t)(m0 + r) * EMBED + kh);
    }
    #pragma unroll
    for (int j = 0; j < 2; j++) {        // B: 128 rows
        int r = row + j * 64;
        cpa16(Bs + r * PITCH + c, Bw + (size_t)(ngl0 + r) * EMBED + kh);
    }
    asm volatile("cp.async.commit_group;\n" ::: "memory");
}

__global__ void __launch_bounds__(256, 2)
gemm_f16(const __half* __restrict__ A, const __half* __restrict__ Bw,
         __half* __restrict__ o0, __half* __restrict__ o1,
         __half* __restrict__ o2,
         float* __restrict__ of, const float* __restrict__ bias)
{
    extern __shared__ __align__(128) char smem[];
    const uint32_t s0 = (uint32_t)__cvta_generic_to_shared(smem);
    const int tid  = threadIdx.x;
    const int lane = tid & 31;
    const int warp = tid >> 5;
    const int g    = lane >> 2;
    const int t    = lane & 3;
    const int wm0  = (warp & 1) * 64;    // warp tile 64x32
    const int wn0  = (warp >> 1) * 32;
    const int m0   = blockIdx.x * BM;
    const int ngl0 = blockIdx.y * BN;    // global B row (= output col) base

    // ldmatrix per-thread address components
    const int rA  = ((lane >> 3) & 1) * 8 + (lane & 7);
    const int kbA = (lane >> 4) * 16;
    const int rB  = ((lane >> 4) & 1) * 8 + (lane & 7);
    const int kbB = ((lane >> 3) & 1) * 16;
    const uint32_t aoff = (uint32_t)((wm0 + rA) * PITCH + kbA);
    const uint32_t boff = (uint32_t)((wn0 + rB) * PITCH + kbB) + A_BYTES;

    float acc[4][4][4];
    #pragma unroll
    for (int i = 0; i < 4; i++)
        #pragma unroll
        for (int j = 0; j < 4; j++)
            #pragma unroll
            for (int r = 0; r < 4; r++) acc[i][j][r] = 0.f;

    const int T = EMBED / BK;   // 32
    load_stage(smem, 0, A, Bw, m0, ngl0, 0, tid);
    load_stage(smem, 1, A, Bw, m0, ngl0, BK, tid);
    load_stage(smem, 2, A, Bw, m0, ngl0, 2 * BK, tid);
    load_stage(smem, 3, A, Bw, m0, ngl0, 3 * BK, tid);

    #pragma unroll 1
    for (int kt = 0; kt < T; ++kt) {
        // Outstanding groups at top of kt cover stages kt..min(kt+3, T-1).
        // Wait until stage kt's group has landed.
        if (kt + 3 < T)      asm volatile("cp.async.wait_group 3;\n" ::: "memory");
        else if (kt + 2 < T) asm volatile("cp.async.wait_group 2;\n" ::: "memory");
        else if (kt + 1 < T) asm volatile("cp.async.wait_group 1;\n" ::: "memory");
        else                 asm volatile("cp.async.wait_group 0;\n" ::: "memory");
        __syncthreads();
        // Prefetch AFTER the barrier (race proof in kernel header)
        if (kt + 4 < T)
            load_stage(smem, (kt + 4) % NSTAGE, A, Bw, m0, ngl0,
                       (kt + 4) * BK, tid);

        const uint32_t su = s0 + (uint32_t)((kt % NSTAGE) * STAGE);

        #pragma unroll
        for (int kc = 0; kc < 2; ++kc) {           // two K=16 chunks
            uint32_t a[4][4], b[4][2];
            #pragma unroll
            for (int mi = 0; mi < 4; ++mi)
                ldsm4(a[mi], su + aoff + (uint32_t)(mi * 16 * PITCH + kc * 32));
            #pragma unroll
            for (int pi = 0; pi < 2; ++pi) {
                uint32_t r[4];
                ldsm4(r, su + boff + (uint32_t)(pi * 16 * PITCH + kc * 32));
                b[2 * pi][0]     = r[0]; b[2 * pi][1]     = r[1];
                b[2 * pi + 1][0] = r[2]; b[2 * pi + 1][1] = r[3];
            }
            #pragma unroll
            for (int mi = 0; mi < 4; ++mi)
                #pragma unroll
                for (int ni = 0; ni < 4; ++ni)
                    mma16816(acc[mi][ni], a[mi], b[ni][0], b[ni][1]);
        }
    }

    // Epilogue
    if (of) {              // fp32 output + bias (final projection), N = EMBED
        #pragma unroll
        for (int mi = 0; mi < 4; ++mi)
            #pragma unroll
            for (int ni = 0; ni < 4; ++ni) {
                int row = m0 + wm0 + mi * 16 + g;
                int col = ngl0 + wn0 + ni * 8 + 2 * t;
                float2 bb = *(const float2*)&bias[col];
                *(float2*)(of + (size_t)row * EMBED + col) =
                    make_float2(acc[mi][ni][0] + bb.x, acc[mi][ni][1] + bb.y);
                *(float2*)(of + (size_t)(row + 8) * EMBED + col) =
                    make_float2(acc[mi][ni][2] + bb.x, acc[mi][ni][3] + bb.y);
            }
    } else {               // fused QKV: select output by blockIdx.y>>3
        int which = blockIdx.y >> 3;              // 1024 cols per output
        __half* C = (which == 0) ? o0 : (which == 1) ? o1 : o2;
        const float sc = (which == 0) ? 0.03125f : 1.0f;  // fold 1/sqrt(1024) into Q
        int cb = (blockIdx.y & 7) * BN;
        #pragma unroll
        for (int mi = 0; mi < 4; ++mi)
            #pragma unroll
            for (int ni = 0; ni < 4; ++ni) {
                int row = m0 + wm0 + mi * 16 + g;
                int col = cb + wn0 + ni * 8 + 2 * t;
                *(__half2*)(C + (size_t)row * EMBED + col) =
                    __floats2half2_rn(acc[mi][ni][0] * sc, acc[mi][ni][1] * sc);
                *(__half2*)(C + (size_t)(row + 8) * EMBED + col) =
                    __floats2half2_rn(acc[mi][ni][2] * sc, acc[mi][ni][3] * sc);
            }
    }
}

// ---------------------------------------------------------------------------
// Tensor-core cross-head attention: one warp per token, 8 tokens per block.
// energy(16x16) = Q(16x64) @ K^T via 8 HMMA; softmax in registers (quad
// shuffles); P repacked acc->A-fragment; AV(16x64) via 8 HMMA with V loaded
// by ldmatrix.trans. No __syncthreads. Q pre-scaled by 1/32.
// ---------------------------------------------------------------------------
#define TPITCH 144                 // bytes per head row in smem (4-bank step)
#define TILE_B (16 * TPITCH)       // 2304 per array
#define TOK_SMEM (3 * TILE_B)      // 6912 per token
#define ATTN_SMEM (8 * TOK_SMEM)   // 55296

__global__ void __launch_bounds__(256, 4)
attn_mma(const __half* __restrict__ Qh, const __half* __restrict__ Kh,
         const __half* __restrict__ Vh, __half* __restrict__ AOh)
{
    extern __shared__ __align__(128) char asmem[];
    const int lane = threadIdx.x & 31;
    const int w    = threadIdx.x >> 5;
    const int tok  = blockIdx.x * 8 + w;
    char* tq = asmem + w * TOK_SMEM;
    char* tk = tq + TILE_B;
    char* tv = tk + TILE_B;

    // Per-warp load of this token's Q/K/V tiles (16x64 fp16 each)
    {
        const __half* gq = Qh + (size_t)tok * EMBED;
        const __half* gk = Kh + (size_t)tok * EMBED;
        const __half* gv = Vh + (size_t)tok * EMBED;
        #pragma unroll
        for (int i = 0; i < 4; i++) {
            int ch  = lane + i * 32;          // 0..127 16B-chunks
            int row = ch >> 3, c16 = (ch & 7) * 16;
            int go  = ch * 8;                 // half offset
            cpa16(tq + row * TPITCH + c16, gq + go);
            cpa16(tk + row * TPITCH + c16, gk + go);
            cpa16(tv + row * TPITCH + c16, gv + go);
        }
        asm volatile("cp.async.commit_group;\n" ::: "memory");
        asm volatile("cp.async.wait_group 0;\n" ::: "memory");
        __syncwarp();
    }

    const uint32_t sq = (uint32_t)__cvta_generic_to_shared(tq);
    const uint32_t sk = (uint32_t)__cvta_generic_to_shared(tk);
    const uint32_t sv = (uint32_t)__cvta_generic_to_shared(tv);

    // Fragment address recipes (A non-trans, B non-trans, B-from-[k][n] trans)
    const uint32_t qoff = (uint32_t)((lane & 15) * TPITCH + (lane >> 4) * 16);
    const uint32_t koff = (uint32_t)(((((lane >> 4) & 1) * 8) + (lane & 7)) * TPITCH
                                     + ((lane >> 3) & 1) * 16);
    const uint32_t voff = (uint32_t)(((((lane >> 3) & 1) * 8) + (lane & 7)) * TPITCH
                                     + ((lane >> 4) & 1) * 16);

    // Energy: e0 = cols(hk) 0-7, e1 = cols 8-15; rows(hq): g (c0,c1), g+8 (c2,c3)
    float e0[4] = {0.f, 0.f, 0.f, 0.f};
    float e1[4] = {0.f, 0.f, 0.f, 0.f};
    #pragma unroll
    for (int kk = 0; kk < 4; kk++) {           // K dim 64 = 4 x k16
        uint32_t a[4], r[4];
        ldsm4(a, sq + qoff + kk * 32);
        ldsm4(r, sk + koff + kk * 32);
        mma16816(e0, a, r[0], r[1]);
        mma16816(e1, a, r[2], r[3]);
    }

    // Softmax over hk within each row; a row lives in a 4-lane quad.
    float mlo = fmaxf(fmaxf(e0[0], e0[1]), fmaxf(e1[0], e1[1]));
    float mhi = fmaxf(fmaxf(e0[2], e0[3]), fmaxf(e1[2], e1[3]));
    mlo = fmaxf(mlo, __shfl_xor_sync(0xffffffffu, mlo, 1));
    mlo = fmaxf(mlo, __shfl_xor_sync(0xffffffffu, mlo, 2));
    mhi = fmaxf(mhi, __shfl_xor_sync(0xffffffffu, mhi, 1));
    mhi = fmaxf(mhi, __shfl_xor_sync(0xffffffffu, mhi, 2));

    float p00 = __expf(e0[0] - mlo), p01 = __expf(e0[1] - mlo);
    float p10 = __expf(e1[0] - mlo), p11 = __expf(e1[1] - mlo);
    float q00 = __expf(e0[2] - mhi), q01 = __expf(e0[3] - mhi);
    float q10 = __expf(e1[2] - mhi), q11 = __expf(e1[3] - mhi);

    float slo = p00 + p01 + p10 + p11;
    float shi = q00 + q01 + q10 + q11;
    slo += __shfl_xor_sync(0xffffffffu, slo, 1);
    slo += __shfl_xor_sync(0xffffffffu, slo, 2);
    shi += __shfl_xor_sync(0xffffffffu, shi, 1);
    shi += __shfl_xor_sync(0xffffffffu, shi, 2);
    const float ilo = 1.f / slo, ihi = 1.f / shi;

    // Repack P as A-fragment (acc->A layout identity)
    uint32_t P[4];
    P[0] = h2_bits(__floats2half2_rn(p00 * ilo, p01 * ilo));
    P[1] = h2_bits(__floats2half2_rn(q00 * ihi, q01 * ihi));
    P[2] = h2_bits(__floats2half2_rn(p10 * ilo, p11 * ilo));
    P[3] = h2_bits(__floats2half2_rn(q10 * ihi, q11 * ihi));

    // AV: out(16x64) = P(16x16) @ V(16x64); V via ldmatrix.trans
    __half* out = AOh + (size_t)tok * EMBED;
    const int g = lane >> 2, t = lane & 3;
    #pragma unroll
    for (int nb = 0; nb < 4; nb++) {           // 4 n16 blocks of dim
        uint32_t r[4];
        ldsm4t(r, sv + voff + nb * 32);
        float o0[4] = {0.f, 0.f, 0.f, 0.f};
        float o1[4] = {0.f, 0.f, 0.f, 0.f};
        mma16816(o0, P, r[0], r[1]);           // cols nb*16 + 0-7
        mma16816(o1, P, r[2], r[3]);           // cols nb*16 + 8-15
        const int c0 = nb * 16 + 2 * t;
        *(__half2*)(out + g * 64 + c0)           = __floats2half2_rn(o0[0], o0[1]);
        *(__half2*)(out + (g + 8) * 64 + c0)     = __floats2half2_rn(o0[2], o0[3]);
        *(__half2*)(out + g * 64 + c0 + 8)       = __floats2half2_rn(o1[0], o1[1]);
        *(__half2*)(out + (g + 8) * 64 + c0 + 8) = __floats2half2_rn(o1[2], o1[3]);
    }
}

// ---------------------------------------------------------------------------
// Launch
// ---------------------------------------------------------------------------
extern "C" void kernel_launch(void* const* d_in, const int* in_sizes, int n_in,
                              void* d_out, int out_size)
{
    const float* x  = (const float*)d_in[0];
    const float* Wq = (const float*)d_in[1];
    const float* Wk = (const float*)d_in[2];
    const float* Wv = (const float*)d_in[3];
    const float* Wo = (const float*)d_in[4];
    const float* bo = (const float*)d_in[5];

    __half *Xh, *WT, *WoT, *Qh, *Kh, *Vh, *AOh;
    cudaGetSymbolAddress((void**)&Xh,  g_Xh);
    cudaGetSymbolAddress((void**)&WT,  g_WT);
    cudaGetSymbolAddress((void**)&WoT, g_WoT);
    cudaGetSymbolAddress((void**)&Qh,  g_Qh);
    cudaGetSymbolAddress((void**)&Kh,  g_Kh);
    cudaGetSymbolAddress((void**)&Vh,  g_Vh);
    cudaGetSymbolAddress((void**)&AOh, g_AOh);

    // Fused prep: z 0-3 = weight transposes, z 4-11 = x conversion
    // (x: SEQ*EMBED/8 = 2,097,152 uint4 = 8192 blocks of 256 threads = 8 z-slices)
    dim3 pg(EMBED / 32, EMBED / 32, 12), pb(32, 8);
    prep_k<<<pg, pb>>>(x, Wq, Wk, Wv, Wo, Xh, WT, WoT);

    cudaFuncSetAttribute(gemm_f16, cudaFuncAttributeMaxDynamicSharedMemorySize,
                         GEMM_SMEM);
    cudaFuncSetAttribute(attn_mma, cudaFuncAttributeMaxDynamicSharedMemorySize,
                         ATTN_SMEM);

    // Fused QKV: N = 3072 (Q output pre-scaled by 1/32 in epilogue)
    dim3 gqkv(SEQ / BM, 3 * EMBED / BN);   // (128, 24)
    gemm_f16<<<gqkv, 256, GEMM_SMEM>>>(Xh, WT, Qh, Kh, Vh, nullptr, nullptr);

    attn_mma<<<SEQ / 8, 256, ATTN_SMEM>>>(Qh, Kh, Vh, AOh);

    // Final projection: N = 1024, fp32 out + bias
    dim3 go(SEQ / BM, EMBED / BN);         // (128, 8)
    gemm_f16<<<go, 256, GEMM_SMEM>>>(AOh, WoT, nullptr, nullptr, nullptr,
                                     (float*)d_out, bo);
}

// round 16
// speedup vs baseline: 1.0111x; 1.0111x over previous
#include <cuda_runtime.h>
#include <cuda_fp16.h>
#include <cstdint>
#include <cstddef>

// Problem constants
#define EMBED 1024
#define SEQ   16384   // 4 * 4096 tokens
#define HEADS 16

// ---------------------------------------------------------------------------
// Scratch (allocation-free rule: __device__ globals)
// ---------------------------------------------------------------------------
__device__ __align__(1024) __half g_Xh [SEQ * EMBED];         // x -> fp16
__device__ __align__(1024) __half g_WT [3 * EMBED * EMBED];   // [Wq;Wk;Wv]^T fp16 [n][k]
__device__ __align__(1024) __half g_WoT[EMBED * EMBED];       // Wo^T fp16 [n][k]
__device__ __align__(1024) __half g_Qh [SEQ * EMBED];         // pre-scaled by 1/32
__device__ __align__(1024) __half g_Kh [SEQ * EMBED];
__device__ __align__(1024) __half g_Vh [SEQ * EMBED];
__device__ __align__(1024) __half g_AOh[SEQ * EMBED];

__device__ __forceinline__ uint32_t h2_bits(__half2 h) {
    union { __half2 h; uint32_t u; } cvt;
    cvt.h = h;
    return cvt.u;
}

// ---------------------------------------------------------------------------
// Fused prep: z<4 -> transpose+convert one weight matrix (32x32 tile grid);
//             z>=4 -> convert an x chunk to fp16 (8 z-slices x 1024 blocks).
// Block: (32, 8) = 256 threads for both paths.
// ---------------------------------------------------------------------------
__global__ void prep_k(const float* __restrict__ x,
                       const float* __restrict__ Wq,
                       const float* __restrict__ Wk,
                       const float* __restrict__ Wv,
                       const float* __restrict__ Wo,
                       __half* __restrict__ Xh,
                       __half* __restrict__ WT,     // 3*E*E
                       __half* __restrict__ WoT) {  // E*E
    const int z = blockIdx.z;
    if (z >= 4) {
        // x -> fp16: 8 halves per thread
        const int tid = threadIdx.y * 32 + threadIdx.x;
        const int blk = (z - 4) * 1024 + blockIdx.y * 32 + blockIdx.x;
        const int i   = blk * 256 + tid;          // uint4 (8-half) index
        const float4* src = (const float4*)x;
        float4 v0 = src[2 * i], v1 = src[2 * i + 1];
        uint4 u;
        u.x = h2_bits(__floats2half2_rn(v0.x, v0.y));
        u.y = h2_bits(__floats2half2_rn(v0.z, v0.w));
        u.z = h2_bits(__floats2half2_rn(v1.x, v1.y));
        u.w = h2_bits(__floats2half2_rn(v1.z, v1.w));
        ((uint4*)Xh)[i] = u;
        return;
    }
    const float* src = (z == 0) ? Wq : (z == 1) ? Wk : (z == 2) ? Wv : Wo;
    __half* dst = (z == 3) ? WoT : WT + (size_t)z * EMBED * EMBED;

    __shared__ float t[32][33];
    const int tx = threadIdx.x, ty = threadIdx.y;
    const int n  = blockIdx.x * 32 + tx;
    const int k0 = blockIdx.y * 32;
    #pragma unroll
    for (int j = 0; j < 32; j += 8)
        t[ty + j][tx] = src[(size_t)(k0 + ty + j) * EMBED + n];
    __syncthreads();
    const int ok  = k0 + tx;
    const int on0 = blockIdx.x * 32;
    #pragma unroll
    for (int j = 0; j < 32; j += 8)
        dst[(size_t)(on0 + ty + j) * EMBED + ok] = __float2half_rn(t[tx][ty + j]);
}

// ---------------------------------------------------------------------------
// FP16 tensor-core GEMM (R14-proven): C[M,N] = A[M,K] @ B[N,K]^T
// Tile 128x128, 8 warps (2M x 4N) of 64x32, BK=32, FOUR-stage cp.async,
// occ 2 (2 x 80KB = 160KB <= 228KB). Single __syncthreads per iteration:
// wait -> sync -> prefetch(kt+3) -> compute. Race-free: stage (kt+3)%4 ==
// (kt-1)%4 was last read in iteration kt-1; the barrier at top of kt
// guarantees all warps passed it.
// ---------------------------------------------------------------------------
#define BM 128
#define BN 128
#define BK 32
#define PITCH 80                       // bytes per smem row (64B data + pad)
#define A_BYTES (BM * PITCH)           // 10240
#define B_BYTES (BN * PITCH)           // 10240
#define STAGE   (A_BYTES + B_BYTES)    // 20480
#define NSTAGE  4
#define GEMM_SMEM (NSTAGE * STAGE)     // 81920

__device__ __forceinline__ void cpa16(void* dst, const void* src) {
    uint32_t d = (uint32_t)__cvta_generic_to_shared(dst);
    asm volatile("cp.async.cg.shared.global [%0], [%1], 16;\n"
                 :: "r"(d), "l"(src));
}

__device__ __forceinline__ void ldsm4(uint32_t* r, uint32_t saddr) {
    asm volatile("ldmatrix.sync.aligned.m8n8.x4.shared.b16 {%0,%1,%2,%3}, [%4];"
                 : "=r"(r[0]), "=r"(r[1]), "=r"(r[2]), "=r"(r[3]) : "r"(saddr));
}

__device__ __forceinline__ void ldsm4t(uint32_t* r, uint32_t saddr) {
    asm volatile("ldmatrix.sync.aligned.m8n8.x4.trans.shared.b16 {%0,%1,%2,%3}, [%4];"
                 : "=r"(r[0]), "=r"(r[1]), "=r"(r[2]), "=r"(r[3]) : "r"(saddr));
}

__device__ __forceinline__ void mma16816(float* c, const uint32_t* a,
                                         uint32_t b0, uint32_t b1) {
    asm volatile("mma.sync.aligned.m16n8k16.row.col.f32.f16.f16.f32 "
        "{%0,%1,%2,%3}, {%4,%5,%6,%7}, {%8,%9}, {%0,%1,%2,%3};\n"
        : "+f"(c[0]), "+f"(c[1]), "+f"(c[2]), "+f"(c[3])
        : "r"(a[0]), "r"(a[1]), "r"(a[2]), "r"(a[3]), "r"(b0), "r"(b1));
}

__device__ __forceinline__ void load_stage(char* sm, int s,
        const __half* __restrict__ A, const __half* __restrict__ Bw,
        int m0, int ngl0, int k0, int tid) {
    char* As = sm + s * STAGE;
    char* Bs = As + A_BYTES;
    const int row = tid >> 2;            // 0..63
    const int c   = (tid & 3) * 16;      // byte offset in 64B row data
    const int kh  = k0 + (tid & 3) * 8;  // half offset
    #pragma unroll
    for (int j = 0; j < 2; j++) {        // A: 128 rows
        int r = row + j * 64;
        cpa16(As + r * PITCH + c, A + (size_t)(m0 + r) * EMBED + kh);
    }
    #pragma unroll
    for (int j = 0; j < 2; j++) {        // B: 128 rows
        int r = row + j * 64;
        cpa16(Bs + r * PITCH + c, Bw + (size_t)(ngl0 + r) * EMBED + kh);
    }
    asm volatile("cp.async.commit_group;\n" ::: "memory");
}

__global__ void __launch_bounds__(256, 2)
gemm_f16(const __half* __restrict__ A, const __half* __restrict__ Bw,
         __half* __restrict__ o0, __half* __restrict__ o1,
         __half* __restrict__ o2,
         float* __restrict__ of, const float* __restrict__ bias)
{
    extern __shared__ __align__(128) char smem[];
    const uint32_t s0 = (uint32_t)__cvta_generic_to_shared(smem);
    const int tid  = threadIdx.x;
    const int lane = tid & 31;
    const int warp = tid >> 5;
    const int g    = lane >> 2;
    const int t    = lane & 3;
    const int wm0  = (warp & 1) * 64;    // warp tile 64x32
    const int wn0  = (warp >> 1) * 32;
    const int m0   = blockIdx.x * BM;
    const int ngl0 = blockIdx.y * BN;    // global B row (= output col) base

    // ldmatrix per-thread address components
    const int rA  = ((lane >> 3) & 1) * 8 + (lane & 7);
    const int kbA = (lane >> 4) * 16;
    const int rB  = ((lane >> 4) & 1) * 8 + (lane & 7);
    const int kbB = ((lane >> 3) & 1) * 16;
    const uint32_t aoff = (uint32_t)((wm0 + rA) * PITCH + kbA);
    const uint32_t boff = (uint32_t)((wn0 + rB) * PITCH + kbB) + A_BYTES;

    float acc[4][4][4];
    #pragma unroll
    for (int i = 0; i < 4; i++)
        #pragma unroll
        for (int j = 0; j < 4; j++)
            #pragma unroll
            for (int r = 0; r < 4; r++) acc[i][j][r] = 0.f;

    const int T = EMBED / BK;   // 32
    load_stage(smem, 0, A, Bw, m0, ngl0, 0, tid);
    load_stage(smem, 1, A, Bw, m0, ngl0, BK, tid);
    load_stage(smem, 2, A, Bw, m0, ngl0, 2 * BK, tid);

    #pragma unroll 1
    for (int kt = 0; kt < T; ++kt) {
        // Outstanding groups at top of kt cover stages kt..min(kt+2, T-1).
        if (kt + 2 < T)      asm volatile("cp.async.wait_group 2;\n" ::: "memory");
        else if (kt + 1 < T) asm volatile("cp.async.wait_group 1;\n" ::: "memory");
        else                 asm volatile("cp.async.wait_group 0;\n" ::: "memory");
        __syncthreads();
        // Prefetch AFTER the barrier (race proof in kernel header)
        if (kt + 3 < T)
            load_stage(smem, (kt + 3) % NSTAGE, A, Bw, m0, ngl0,
                       (kt + 3) * BK, tid);

        const uint32_t su = s0 + (uint32_t)((kt % NSTAGE) * STAGE);

        #pragma unroll
        for (int kc = 0; kc < 2; ++kc) {           // two K=16 chunks
            uint32_t a[4][4], b[4][2];
            #pragma unroll
            for (int mi = 0; mi < 4; ++mi)
                ldsm4(a[mi], su + aoff + (uint32_t)(mi * 16 * PITCH + kc * 32));
            #pragma unroll
            for (int pi = 0; pi < 2; ++pi) {
                uint32_t r[4];
                ldsm4(r, su + boff + (uint32_t)(pi * 16 * PITCH + kc * 32));
                b[2 * pi][0]     = r[0]; b[2 * pi][1]     = r[1];
                b[2 * pi + 1][0] = r[2]; b[2 * pi + 1][1] = r[3];
            }
            #pragma unroll
            for (int mi = 0; mi < 4; ++mi)
                #pragma unroll
                for (int ni = 0; ni < 4; ++ni)
                    mma16816(acc[mi][ni], a[mi], b[ni][0], b[ni][1]);
        }
    }

    // Epilogue
    if (of) {              // fp32 output + bias (final projection), N = EMBED
        #pragma unroll
        for (int mi = 0; mi < 4; ++mi)
            #pragma unroll
            for (int ni = 0; ni < 4; ++ni) {
                int row = m0 + wm0 + mi * 16 + g;
                int col = ngl0 + wn0 + ni * 8 + 2 * t;
                float2 bb = *(const float2*)&bias[col];
                *(float2*)(of + (size_t)row * EMBED + col) =
                    make_float2(acc[mi][ni][0] + bb.x, acc[mi][ni][1] + bb.y);
                *(float2*)(of + (size_t)(row + 8) * EMBED + col) =
                    make_float2(acc[mi][ni][2] + bb.x, acc[mi][ni][3] + bb.y);
            }
    } else {               // fused QKV: select output by blockIdx.y>>3
        int which = blockIdx.y >> 3;              // 1024 cols per output
        __half* C = (which == 0) ? o0 : (which == 1) ? o1 : o2;
        const float sc = (which == 0) ? 0.03125f : 1.0f;  // fold 1/sqrt(1024) into Q
        int cb = (blockIdx.y & 7) * BN;
        #pragma unroll
        for (int mi = 0; mi < 4; ++mi)
            #pragma unroll
            for (int ni = 0; ni < 4; ++ni) {
                int row = m0 + wm0 + mi * 16 + g;
                int col = cb + wn0 + ni * 8 + 2 * t;
                *(__half2*)(C + (size_t)row * EMBED + col) =
                    __floats2half2_rn(acc[mi][ni][0] * sc, acc[mi][ni][1] * sc);
                *(__half2*)(C + (size_t)(row + 8) * EMBED + col) =
                    __floats2half2_rn(acc[mi][ni][2] * sc, acc[mi][ni][3] * sc);
            }
    }
}

// ---------------------------------------------------------------------------
// Tensor-core cross-head attention: one warp per token, 8 tokens per block.
// energy(16x16) = Q(16x64) @ K^T via 8 HMMA; softmax in registers (quad
// shuffles); P repacked acc->A-fragment; AV(16x64) via 8 HMMA with V loaded
// by ldmatrix.trans. No __syncthreads. Q pre-scaled by 1/32.
// ---------------------------------------------------------------------------
#define TPITCH 144                 // bytes per head row in smem (4-bank step)
#define TILE_B (16 * TPITCH)       // 2304 per array
#define TOK_SMEM (3 * TILE_B)      // 6912 per token
#define ATTN_SMEM (8 * TOK_SMEM)   // 55296

__global__ void __launch_bounds__(256, 4)
attn_mma(const __half* __restrict__ Qh, const __half* __restrict__ Kh,
         const __half* __restrict__ Vh, __half* __restrict__ AOh)
{
    extern __shared__ __align__(128) char asmem[];
    const int lane = threadIdx.x & 31;
    const int w    = threadIdx.x >> 5;
    const int tok  = blockIdx.x * 8 + w;
    char* tq = asmem + w * TOK_SMEM;
    char* tk = tq + TILE_B;
    char* tv = tk + TILE_B;

    // Per-warp load of this token's Q/K/V tiles (16x64 fp16 each)
    {
        const __half* gq = Qh + (size_t)tok * EMBED;
        const __half* gk = Kh + (size_t)tok * EMBED;
        const __half* gv = Vh + (size_t)tok * EMBED;
        #pragma unroll
        for (int i = 0; i < 4; i++) {
            int ch  = lane + i * 32;          // 0..127 16B-chunks
            int row = ch >> 3, c16 = (ch & 7) * 16;
            int go  = ch * 8;                 // half offset
            cpa16(tq + row * TPITCH + c16, gq + go);
            cpa16(tk + row * TPITCH + c16, gk + go);
            cpa16(tv + row * TPITCH + c16, gv + go);
        }
        asm volatile("cp.async.commit_group;\n" ::: "memory");
        asm volatile("cp.async.wait_group 0;\n" ::: "memory");
        __syncwarp();
    }

    const uint32_t sq = (uint32_t)__cvta_generic_to_shared(tq);
    const uint32_t sk = (uint32_t)__cvta_generic_to_shared(tk);
    const uint32_t sv = (uint32_t)__cvta_generic_to_shared(tv);

    // Fragment address recipes (A non-trans, B non-trans, B-from-[k][n] trans)
    const uint32_t qoff = (uint32_t)((lane & 15) * TPITCH + (lane >> 4) * 16);
    const uint32_t koff = (uint32_t)(((((lane >> 4) & 1) * 8) + (lane & 7)) * TPITCH
                                     + ((lane >> 3) & 1) * 16);
    const uint32_t voff = (uint32_t)(((((lane >> 3) & 1) * 8) + (lane & 7)) * TPITCH
                                     + ((lane >> 4) & 1) * 16);

    // Energy: e0 = cols(hk) 0-7, e1 = cols 8-15; rows(hq): g (c0,c1), g+8 (c2,c3)
    float e0[4] = {0.f, 0.f, 0.f, 0.f};
    float e1[4] = {0.f, 0.f, 0.f, 0.f};
    #pragma unroll
    for (int kk = 0; kk < 4; kk++) {           // K dim 64 = 4 x k16
        uint32_t a[4], r[4];
        ldsm4(a, sq + qoff + kk * 32);
        ldsm4(r, sk + koff + kk * 32);
        mma16816(e0, a, r[0], r[1]);
        mma16816(e1, a, r[2], r[3]);
    }

    // Softmax over hk within each row; a row lives in a 4-lane quad.
    float mlo = fmaxf(fmaxf(e0[0], e0[1]), fmaxf(e1[0], e1[1]));
    float mhi = fmaxf(fmaxf(e0[2], e0[3]), fmaxf(e1[2], e1[3]));
    mlo = fmaxf(mlo, __shfl_xor_sync(0xffffffffu, mlo, 1));
    mlo = fmaxf(mlo, __shfl_xor_sync(0xffffffffu, mlo, 2));
    mhi = fmaxf(mhi, __shfl_xor_sync(0xffffffffu, mhi, 1));
    mhi = fmaxf(mhi, __shfl_xor_sync(0xffffffffu, mhi, 2));

    float p00 = __expf(e0[0] - mlo), p01 = __expf(e0[1] - mlo);
    float p10 = __expf(e1[0] - mlo), p11 = __expf(e1[1] - mlo);
    float q00 = __expf(e0[2] - mhi), q01 = __expf(e0[3] - mhi);
    float q10 = __expf(e1[2] - mhi), q11 = __expf(e1[3] - mhi);

    float slo = p00 + p01 + p10 + p11;
    float shi = q00 + q01 + q10 + q11;
    slo += __shfl_xor_sync(0xffffffffu, slo, 1);
    slo += __shfl_xor_sync(0xffffffffu, slo, 2);
    shi += __shfl_xor_sync(0xffffffffu, shi, 1);
    shi += __shfl_xor_sync(0xffffffffu, shi, 2);
    const float ilo = 1.f / slo, ihi = 1.f / shi;

    // Repack P as A-fragment (acc->A layout identity)
    uint32_t P[4];
    P[0] = h2_bits(__floats2half2_rn(p00 * ilo, p01 * ilo));
    P[1] = h2_bits(__floats2half2_rn(q00 * ihi, q01 * ihi));
    P[2] = h2_bits(__floats2half2_rn(p10 * ilo, p11 * ilo));
    P[3] = h2_bits(__floats2half2_rn(q10 * ihi, q11 * ihi));

    // AV: out(16x64) = P(16x16) @ V(16x64); V via ldmatrix.trans
    __half* out = AOh + (size_t)tok * EMBED;
    const int g = lane >> 2, t = lane & 3;
    #pragma unroll
    for (int nb = 0; nb < 4; nb++) {           // 4 n16 blocks of dim
        uint32_t r[4];
        ldsm4t(r, sv + voff + nb * 32);
        float o0[4] = {0.f, 0.f, 0.f, 0.f};
        float o1[4] = {0.f, 0.f, 0.f, 0.f};
        mma16816(o0, P, r[0], r[1]);           // cols nb*16 + 0-7
        mma16816(o1, P, r[2], r[3]);           // cols nb*16 + 8-15
        const int c0 = nb * 16 + 2 * t;
        *(__half2*)(out + g * 64 + c0)           = __floats2half2_rn(o0[0], o0[1]);
        *(__half2*)(out + (g + 8) * 64 + c0)     = __floats2half2_rn(o0[2], o0[3]);
        *(__half2*)(out + g * 64 + c0 + 8)       = __floats2half2_rn(o1[0], o1[1]);
        *(__half2*)(out + (g + 8) * 64 + c0 + 8) = __floats2half2_rn(o1[2], o1[3]);
    }
}

// ---------------------------------------------------------------------------
// Launch
// ---------------------------------------------------------------------------
extern "C" void kernel_launch(void* const* d_in, const int* in_sizes, int n_in,
                              void* d_out, int out_size)
{
    const float* x  = (const float*)d_in[0];
    const float* Wq = (const float*)d_in[1];
    const float* Wk = (const float*)d_in[2];
    const float* Wv = (const float*)d_in[3];
    const float* Wo = (const float*)d_in[4];
    const float* bo = (const float*)d_in[5];

    __half *Xh, *WT, *WoT, *Qh, *Kh, *Vh, *AOh;
    cudaGetSymbolAddress((void**)&Xh,  g_Xh);
    cudaGetSymbolAddress((void**)&WT,  g_WT);
    cudaGetSymbolAddress((void**)&WoT, g_WoT);
    cudaGetSymbolAddress((void**)&Qh,  g_Qh);
    cudaGetSymbolAddress((void**)&Kh,  g_Kh);
    cudaGetSymbolAddress((void**)&Vh,  g_Vh);
    cudaGetSymbolAddress((void**)&AOh, g_AOh);

    // Fused prep: z 0-3 = weight transposes, z 4-11 = x conversion
    dim3 pg(EMBED / 32, EMBED / 32, 12), pb(32, 8);
    prep_k<<<pg, pb>>>(x, Wq, Wk, Wv, Wo, Xh, WT, WoT);

    cudaFuncSetAttribute(gemm_f16, cudaFuncAttributeMaxDynamicSharedMemorySize,
                         GEMM_SMEM);
    cudaFuncSetAttribute(attn_mma, cudaFuncAttributeMaxDynamicSharedMemorySize,
                         ATTN_SMEM);

    // Fused QKV: N = 3072 (Q output pre-scaled by 1/32 in epilogue)
    dim3 gqkv(SEQ / BM, 3 * EMBED / BN);   // (128, 24)
    gemm_f16<<<gqkv, 256, GEMM_SMEM>>>(Xh, WT, Qh, Kh, Vh, nullptr, nullptr);

    attn_mma<<<SEQ / 8, 256, ATTN_SMEM>>>(Qh, Kh, Vh, AOh);

    // Final projection: N = 1024, fp32 out + bias
    dim3 go(SEQ / BM, EMBED / BN);         // (128, 8)
    gemm_f16<<<go, 256, GEMM_SMEM>>>(AOh, WoT, nullptr, nullptr, nullptr,
                                     (float*)d_out, bo);
}

// round 17
// speedup vs baseline: 1.1115x; 1.0993x over previous
#include <cuda_runtime.h>
#include <cuda_fp16.h>
#include <cstdint>
#include <cstddef>

// Problem constants
#define EMBED 1024
#define SEQ   16384   // 4 * 4096 tokens
#define HEADS 16

// ---------------------------------------------------------------------------
// Scratch (allocation-free rule: __device__ globals)
// ---------------------------------------------------------------------------
__device__ __align__(1024) __half g_Xh [SEQ * EMBED];         // x -> fp16
__device__ __align__(1024) __half g_WT [3 * EMBED * EMBED];   // [Wq;Wk;Wv]^T fp16 [n][k]
__device__ __align__(1024) __half g_WoT[EMBED * EMBED];       // Wo^T fp16 [n][k]
__device__ __align__(1024) __half g_Qh [SEQ * EMBED];         // pre-scaled by 1/32
__device__ __align__(1024) __half g_Kh [SEQ * EMBED];
__device__ __align__(1024) __half g_Vh [SEQ * EMBED];
__device__ __align__(1024) __half g_AOh[SEQ * EMBED];

__device__ __forceinline__ uint32_t h2_bits(__half2 h) {
    union { __half2 h; uint32_t u; } cvt;
    cvt.h = h;
    return cvt.u;
}

// ---------------------------------------------------------------------------
// Fused prep: z<4 -> transpose+convert one weight matrix (32x32 tile grid);
//             z>=4 -> convert an x chunk to fp16 (8 z-slices x 1024 blocks).
// Block: (32, 8) = 256 threads for both paths.
// ---------------------------------------------------------------------------
__global__ void prep_k(const float* __restrict__ x,
                       const float* __restrict__ Wq,
                       const float* __restrict__ Wk,
                       const float* __restrict__ Wv,
                       const float* __restrict__ Wo,
                       __half* __restrict__ Xh,
                       __half* __restrict__ WT,     // 3*E*E
                       __half* __restrict__ WoT) {  // E*E
    const int z = blockIdx.z;
    if (z >= 4) {
        // x -> fp16: 8 halves per thread
        const int tid = threadIdx.y * 32 + threadIdx.x;
        const int blk = (z - 4) * 1024 + blockIdx.y * 32 + blockIdx.x;
        const int i   = blk * 256 + tid;          // uint4 (8-half) index
        const float4* src = (const float4*)x;
        float4 v0 = src[2 * i], v1 = src[2 * i + 1];
        uint4 u;
        u.x = h2_bits(__floats2half2_rn(v0.x, v0.y));
        u.y = h2_bits(__floats2half2_rn(v0.z, v0.w));
        u.z = h2_bits(__floats2half2_rn(v1.x, v1.y));
        u.w = h2_bits(__floats2half2_rn(v1.z, v1.w));
        ((uint4*)Xh)[i] = u;
        return;
    }
    const float* src = (z == 0) ? Wq : (z == 1) ? Wk : (z == 2) ? Wv : Wo;
    __half* dst = (z == 3) ? WoT : WT + (size_t)z * EMBED * EMBED;

    __shared__ float t[32][33];
    const int tx = threadIdx.x, ty = threadIdx.y;
    const int n  = blockIdx.x * 32 + tx;
    const int k0 = blockIdx.y * 32;
    #pragma unroll
    for (int j = 0; j < 32; j += 8)
        t[ty + j][tx] = src[(size_t)(k0 + ty + j) * EMBED + n];
    __syncthreads();
    const int ok  = k0 + tx;
    const int on0 = blockIdx.x * 32;
    #pragma unroll
    for (int j = 0; j < 32; j += 8)
        dst[(size_t)(on0 + ty + j) * EMBED + ok] = __float2half_rn(t[tx][ty + j]);
}

// ---------------------------------------------------------------------------
// FP16 tensor-core GEMM: C[M,N] = A[M,K] @ B[N,K]^T
// Tile 128x128, 8 warps (2M x 4N) of 64x32, BK=32, FIVE-stage cp.async,
// prefetch distance 3, __syncthreads every OTHER iteration.
// occ 2 (2 x 100KB = 200KB <= 228KB).
//
// Safety: at even kt, wait_group 1 forces stages kt AND kt+1 landed; the
// barrier publishes both. Odd kt needs no barrier (its stage was published
// at the preceding even barrier). Prefetch at iteration j writes stage
// (j+3)%5 == (j-2)%5, last read at iteration j-2; max inter-warp skew
// between barriers is 1 iteration, and the preceding even barrier
// guarantees all warps completed >= j-1 >= j-2.
// ---------------------------------------------------------------------------
#define BM 128
#define BN 128
#define BK 32
#define PITCH 80                       // bytes per smem row (64B data + pad)
#define A_BYTES (BM * PITCH)           // 10240
#define B_BYTES (BN * PITCH)           // 10240
#define STAGE   (A_BYTES + B_BYTES)    // 20480
#define NSTAGE  5
#define GEMM_SMEM (NSTAGE * STAGE)     // 102400

__device__ __forceinline__ void cpa16(void* dst, const void* src) {
    uint32_t d = (uint32_t)__cvta_generic_to_shared(dst);
    asm volatile("cp.async.cg.shared.global [%0], [%1], 16;\n"
                 :: "r"(d), "l"(src));
}

__device__ __forceinline__ void ldsm4(uint32_t* r, uint32_t saddr) {
    asm volatile("ldmatrix.sync.aligned.m8n8.x4.shared.b16 {%0,%1,%2,%3}, [%4];"
                 : "=r"(r[0]), "=r"(r[1]), "=r"(r[2]), "=r"(r[3]) : "r"(saddr));
}

__device__ __forceinline__ void ldsm4t(uint32_t* r, uint32_t saddr) {
    asm volatile("ldmatrix.sync.aligned.m8n8.x4.trans.shared.b16 {%0,%1,%2,%3}, [%4];"
                 : "=r"(r[0]), "=r"(r[1]), "=r"(r[2]), "=r"(r[3]) : "r"(saddr));
}

__device__ __forceinline__ void mma16816(float* c, const uint32_t* a,
                                         uint32_t b0, uint32_t b1) {
    asm volatile("mma.sync.aligned.m16n8k16.row.col.f32.f16.f16.f32 "
        "{%0,%1,%2,%3}, {%4,%5,%6,%7}, {%8,%9}, {%0,%1,%2,%3};\n"
        : "+f"(c[0]), "+f"(c[1]), "+f"(c[2]), "+f"(c[3])
        : "r"(a[0]), "r"(a[1]), "r"(a[2]), "r"(a[3]), "r"(b0), "r"(b1));
}

__device__ __forceinline__ void load_stage(char* sm, int s,
        const __half* __restrict__ A, const __half* __restrict__ Bw,
        int m0, int ngl0, int k0, int tid) {
    char* As = sm + s * STAGE;
    char* Bs = As + A_BYTES;
    const int row = tid >> 2;            // 0..63
    const int c   = (tid & 3) * 16;      // byte offset in 64B row data
    const int kh  = k0 + (tid & 3) * 8;  // half offset
    #pragma unroll
    for (int j = 0; j < 2; j++) {        // A: 128 rows
        int r = row + j * 64;
        cpa16(As + r * PITCH + c, A + (size_t)(m0 + r) * EMBED + kh);
    }
    #pragma unroll
    for (int j = 0; j < 2; j++) {        // B: 128 rows
        int r = row + j * 64;
        cpa16(Bs + r * PITCH + c, Bw + (size_t)(ngl0 + r) * EMBED + kh);
    }
    asm volatile("cp.async.commit_group;\n" ::: "memory");
}

__global__ void __launch_bounds__(256, 2)
gemm_f16(const __half* __restrict__ A, const __half* __restrict__ Bw,
         __half* __restrict__ o0, __half* __restrict__ o1,
         __half* __restrict__ o2,
         float* __restrict__ of, const float* __restrict__ bias)
{
    extern __shared__ __align__(128) char smem[];
    const uint32_t s0 = (uint32_t)__cvta_generic_to_shared(smem);
    const int tid  = threadIdx.x;
    const int lane = tid & 31;
    const int warp = tid >> 5;
    const int g    = lane >> 2;
    const int t    = lane & 3;
    const int wm0  = (warp & 1) * 64;    // warp tile 64x32
    const int wn0  = (warp >> 1) * 32;
    const int m0   = blockIdx.x * BM;
    const int ngl0 = blockIdx.y * BN;    // global B row (= output col) base

    // ldmatrix per-thread address components
    const int rA  = ((lane >> 3) & 1) * 8 + (lane & 7);
    const int kbA = (lane >> 4) * 16;
    const int rB  = ((lane >> 4) & 1) * 8 + (lane & 7);
    const int kbB = ((lane >> 3) & 1) * 16;
    const uint32_t aoff = (uint32_t)((wm0 + rA) * PITCH + kbA);
    const uint32_t boff = (uint32_t)((wn0 + rB) * PITCH + kbB) + A_BYTES;

    float acc[4][4][4];
    #pragma unroll
    for (int i = 0; i < 4; i++)
        #pragma unroll
        for (int j = 0; j < 4; j++)
            #pragma unroll
            for (int r = 0; r < 4; r++) acc[i][j][r] = 0.f;

    const int T = EMBED / BK;   // 32
    load_stage(smem, 0, A, Bw, m0, ngl0, 0, tid);
    load_stage(smem, 1, A, Bw, m0, ngl0, BK, tid);
    load_stage(smem, 2, A, Bw, m0, ngl0, 2 * BK, tid);

    #pragma unroll 1
    for (int kt = 0; kt < T; ++kt) {
        if ((kt & 1) == 0) {
            // Ensure stages kt AND kt+1 have landed, then publish both.
            if (kt + 2 < T) asm volatile("cp.async.wait_group 1;\n" ::: "memory");
            else            asm volatile("cp.async.wait_group 0;\n" ::: "memory");
            __syncthreads();
        }
        // Prefetch (race proof in kernel header)
        if (kt + 3 < T)
            load_stage(smem, (kt + 3) % NSTAGE, A, Bw, m0, ngl0,
                       (kt + 3) * BK, tid);

        const uint32_t su = s0 + (uint32_t)((kt % NSTAGE) * STAGE);

        #pragma unroll
        for (int kc = 0; kc < 2; ++kc) {           // two K=16 chunks
            uint32_t a[4][4], b[4][2];
            #pragma unroll
            for (int mi = 0; mi < 4; ++mi)
                ldsm4(a[mi], su + aoff + (uint32_t)(mi * 16 * PITCH + kc * 32));
            #pragma unroll
            for (int pi = 0; pi < 2; ++pi) {
                uint32_t r[4];
                ldsm4(r, su + boff + (uint32_t)(pi * 16 * PITCH + kc * 32));
                b[2 * pi][0]     = r[0]; b[2 * pi][1]     = r[1];
                b[2 * pi + 1][0] = r[2]; b[2 * pi + 1][1] = r[3];
            }
            #pragma unroll
            for (int mi = 0; mi < 4; ++mi)
                #pragma unroll
                for (int ni = 0; ni < 4; ++ni)
                    mma16816(acc[mi][ni], a[mi], b[ni][0], b[ni][1]);
        }
    }

    // Epilogue
    if (of) {              // fp32 output + bias (final projection), N = EMBED
        #pragma unroll
        for (int mi = 0; mi < 4; ++mi)
            #pragma unroll
            for (int ni = 0; ni < 4; ++ni) {
                int row = m0 + wm0 + mi * 16 + g;
                int col = ngl0 + wn0 + ni * 8 + 2 * t;
                float2 bb = *(const float2*)&bias[col];
                *(float2*)(of + (size_t)row * EMBED + col) =
                    make_float2(acc[mi][ni][0] + bb.x, acc[mi][ni][1] + bb.y);
                *(float2*)(of + (size_t)(row + 8) * EMBED + col) =
                    make_float2(acc[mi][ni][2] + bb.x, acc[mi][ni][3] + bb.y);
            }
    } else {               // fused QKV: select output by blockIdx.y>>3
        int which = blockIdx.y >> 3;              // 1024 cols per output
        __half* C = (which == 0) ? o0 : (which == 1) ? o1 : o2;
        const float sc = (which == 0) ? 0.03125f : 1.0f;  // fold 1/sqrt(1024) into Q
        int cb = (blockIdx.y & 7) * BN;
        #pragma unroll
        for (int mi = 0; mi < 4; ++mi)
            #pragma unroll
            for (int ni = 0; ni < 4; ++ni) {
                int row = m0 + wm0 + mi * 16 + g;
                int col = cb + wn0 + ni * 8 + 2 * t;
                *(__half2*)(C + (size_t)row * EMBED + col) =
                    __floats2half2_rn(acc[mi][ni][0] * sc, acc[mi][ni][1] * sc);
                *(__half2*)(C + (size_t)(row + 8) * EMBED + col) =
                    __floats2half2_rn(acc[mi][ni][2] * sc, acc[mi][ni][3] * sc);
            }
    }
}

// ---------------------------------------------------------------------------
// Tensor-core cross-head attention: one warp per token, 8 tokens per block.
// energy(16x16) = Q(16x64) @ K^T via 8 HMMA; softmax in registers (quad
// shuffles); P repacked acc->A-fragment; AV(16x64) via 8 HMMA with V loaded
// by ldmatrix.trans. No __syncthreads. Q pre-scaled by 1/32.
// ---------------------------------------------------------------------------
#define TPITCH 144                 // bytes per head row in smem (4-bank step)
#define TILE_B (16 * TPITCH)       // 2304 per array
#define TOK_SMEM (3 * TILE_B)      // 6912 per token
#define ATTN_SMEM (8 * TOK_SMEM)   // 55296

__global__ void __launch_bounds__(256, 4)
attn_mma(const __half* __restrict__ Qh, const __half* __restrict__ Kh,
         const __half* __restrict__ Vh, __half* __restrict__ AOh)
{
    extern __shared__ __align__(128) char asmem[];
    const int lane = threadIdx.x & 31;
    const int w    = threadIdx.x >> 5;
    const int tok  = blockIdx.x * 8 + w;
    char* tq = asmem + w * TOK_SMEM;
    char* tk = tq + TILE_B;
    char* tv = tk + TILE_B;

    // Per-warp load of this token's Q/K/V tiles (16x64 fp16 each)
    {
        const __half* gq = Qh + (size_t)tok * EMBED;
        const __half* gk = Kh + (size_t)tok * EMBED;
        const __half* gv = Vh + (size_t)tok * EMBED;
        #pragma unroll
        for (int i = 0; i < 4; i++) {
            int ch  = lane + i * 32;          // 0..127 16B-chunks
            int row = ch >> 3, c16 = (ch & 7) * 16;
            int go  = ch * 8;                 // half offset
            cpa16(tq + row * TPITCH + c16, gq + go);
            cpa16(tk + row * TPITCH + c16, gk + go);
            cpa16(tv + row * TPITCH + c16, gv + go);
        }
        asm volatile("cp.async.commit_group;\n" ::: "memory");
        asm volatile("cp.async.wait_group 0;\n" ::: "memory");
        __syncwarp();
    }

    const uint32_t sq = (uint32_t)__cvta_generic_to_shared(tq);
    const uint32_t sk = (uint32_t)__cvta_generic_to_shared(tk);
    const uint32_t sv = (uint32_t)__cvta_generic_to_shared(tv);

    // Fragment address recipes (A non-trans, B non-trans, B-from-[k][n] trans)
    const uint32_t qoff = (uint32_t)((lane & 15) * TPITCH + (lane >> 4) * 16);
    const uint32_t koff = (uint32_t)(((((lane >> 4) & 1) * 8) + (lane & 7)) * TPITCH
                                     + ((lane >> 3) & 1) * 16);
    const uint32_t voff = (uint32_t)(((((lane >> 3) & 1) * 8) + (lane & 7)) * TPITCH
                                     + ((lane >> 4) & 1) * 16);

    // Energy: e0 = cols(hk) 0-7, e1 = cols 8-15; rows(hq): g (c0,c1), g+8 (c2,c3)
    float e0[4] = {0.f, 0.f, 0.f, 0.f};
    float e1[4] = {0.f, 0.f, 0.f, 0.f};
    #pragma unroll
    for (int kk = 0; kk < 4; kk++) {           // K dim 64 = 4 x k16
        uint32_t a[4], r[4];
        ldsm4(a, sq + qoff + kk * 32);
        ldsm4(r, sk + koff + kk * 32);
        mma16816(e0, a, r[0], r[1]);
        mma16816(e1, a, r[2], r[3]);
    }

    // Softmax over hk within each row; a row lives in a 4-lane quad.
    float mlo = fmaxf(fmaxf(e0[0], e0[1]), fmaxf(e1[0], e1[1]));
    float mhi = fmaxf(fmaxf(e0[2], e0[3]), fmaxf(e1[2], e1[3]));
    mlo = fmaxf(mlo, __shfl_xor_sync(0xffffffffu, mlo, 1));
    mlo = fmaxf(mlo, __shfl_xor_sync(0xffffffffu, mlo, 2));
    mhi = fmaxf(mhi, __shfl_xor_sync(0xffffffffu, mhi, 1));
    mhi = fmaxf(mhi, __shfl_xor_sync(0xffffffffu, mhi, 2));

    float p00 = __expf(e0[0] - mlo), p01 = __expf(e0[1] - mlo);
    float p10 = __expf(e1[0] - mlo), p11 = __expf(e1[1] - mlo);
    float q00 = __expf(e0[2] - mhi), q01 = __expf(e0[3] - mhi);
    float q10 = __expf(e1[2] - mhi), q11 = __expf(e1[3] - mhi);

    float slo = p00 + p01 + p10 + p11;
    float shi = q00 + q01 + q10 + q11;
    slo += __shfl_xor_sync(0xffffffffu, slo, 1);
    slo += __shfl_xor_sync(0xffffffffu, slo, 2);
    shi += __shfl_xor_sync(0xffffffffu, shi, 1);
    shi += __shfl_xor_sync(0xffffffffu, shi, 2);
    const float ilo = 1.f / slo, ihi = 1.f / shi;

    // Repack P as A-fragment (acc->A layout identity)
    uint32_t P[4];
    P[0] = h2_bits(__floats2half2_rn(p00 * ilo, p01 * ilo));
    P[1] = h2_bits(__floats2half2_rn(q00 * ihi, q01 * ihi));
    P[2] = h2_bits(__floats2half2_rn(p10 * ilo, p11 * ilo));
    P[3] = h2_bits(__floats2half2_rn(q10 * ihi, q11 * ihi));

    // AV: out(16x64) = P(16x16) @ V(16x64); V via ldmatrix.trans
    __half* out = AOh + (size_t)tok * EMBED;
    const int g = lane >> 2, t = lane & 3;
    #pragma unroll
    for (int nb = 0; nb < 4; nb++) {           // 4 n16 blocks of dim
        uint32_t r[4];
        ldsm4t(r, sv + voff + nb * 32);
        float o0[4] = {0.f, 0.f, 0.f, 0.f};
        float o1[4] = {0.f, 0.f, 0.f, 0.f};
        mma16816(o0, P, r[0], r[1]);           // cols nb*16 + 0-7
        mma16816(o1, P, r[2], r[3]);           // cols nb*16 + 8-15
        const int c0 = nb * 16 + 2 * t;
        *(__half2*)(out + g * 64 + c0)           = __floats2half2_rn(o0[0], o0[1]);
        *(__half2*)(out + (g + 8) * 64 + c0)     = __floats2half2_rn(o0[2], o0[3]);
        *(__half2*)(out + g * 64 + c0 + 8)       = __floats2half2_rn(o1[0], o1[1]);
        *(__half2*)(out + (g + 8) * 64 + c0 + 8) = __floats2half2_rn(o1[2], o1[3]);
    }
}

// ---------------------------------------------------------------------------
// Launch
// ---------------------------------------------------------------------------
extern "C" void kernel_launch(void* const* d_in, const int* in_sizes, int n_in,
                              void* d_out, int out_size)
{
    const float* x  = (const float*)d_in[0];
    const float* Wq = (const float*)d_in[1];
    const float* Wk = (const float*)d_in[2];
    const float* Wv = (const float*)d_in[3];
    const float* Wo = (const float*)d_in[4];
    const float* bo = (const float*)d_in[5];

    __half *Xh, *WT, *WoT, *Qh, *Kh, *Vh, *AOh;
    cudaGetSymbolAddress((void**)&Xh,  g_Xh);
    cudaGetSymbolAddress((void**)&WT,  g_WT);
    cudaGetSymbolAddress((void**)&WoT, g_WoT);
    cudaGetSymbolAddress((void**)&Qh,  g_Qh);
    cudaGetSymbolAddress((void**)&Kh,  g_Kh);
    cudaGetSymbolAddress((void**)&Vh,  g_Vh);
    cudaGetSymbolAddress((void**)&AOh, g_AOh);

    // Fused prep: z 0-3 = weight transposes, z 4-11 = x conversion
    dim3 pg(EMBED / 32, EMBED / 32, 12), pb(32, 8);
    prep_k<<<pg, pb>>>(x, Wq, Wk, Wv, Wo, Xh, WT, WoT);

    cudaFuncSetAttribute(gemm_f16, cudaFuncAttributeMaxDynamicSharedMemorySize,
                         GEMM_SMEM);
    cudaFuncSetAttribute(attn_mma, cudaFuncAttributeMaxDynamicSharedMemorySize,
                         ATTN_SMEM);

    // Fused QKV: N = 3072 (Q output pre-scaled by 1/32 in epilogue)
    dim3 gqkv(SEQ / BM, 3 * EMBED / BN);   // (128, 24)
    gemm_f16<<<gqkv, 256, GEMM_SMEM>>>(Xh, WT, Qh, Kh, Vh, nullptr, nullptr);

    attn_mma<<<SEQ / 8, 256, ATTN_SMEM>>>(Qh, Kh, Vh, AOh);

    // Final projection: N = 1024, fp32 out + bias
    dim3 go(SEQ / BM, EMBED / BN);         // (128, 8)
    gemm_f16<<<go, 256, GEMM_SMEM>>>(AOh, WoT, nullptr, nullptr, nullptr,
                                     (float*)d_out, bo);
}